// round 12
// baseline (speedup 1.0000x reference)
#include <cuda_runtime.h>
#include <cuda_fp16.h>
#include <cstdint>
#include <math.h>

// Problem constants
#define BB 4
#define LL 13125
#define MM (BB * LL)      // 52500 rows
#define DD 256
#define NH 8
#define HD 32
#define NLV 3
#define NPT 4
#define DFF 1024
#define EPS 1e-5f

__device__ __constant__ int c_H[NLV] = {100, 50, 25};
__device__ __constant__ int c_W[NLV] = {100, 50, 25};
__device__ __constant__ int c_start[NLV] = {0, 10000, 12500};

// ---------------- scratch ----------------
__device__ __half g_qh[MM * DD];
__device__ __half g_srch[MM * DD];
__device__ __half g_valh[MM * DD];
__device__ float  g_offattn[MM * 288];
__device__ __half g_samph[MM * DD];
__device__ __half g_xh[MM * DD];
__device__ __half g_hh[MM * DFF];
__device__ __half g_wvT[DD * DD];
__device__ __half g_woaT[288 * DD];
__device__ __half g_woutT[DD * DD];
__device__ __half g_wff1T[DFF * DD];
__device__ __half g_wff2T[DD * DFF];
__device__ float  g_boa[288];

// ---------------- fused weight convert/transpose + bias concat ----------------
#define CV0 (DD*DD)
#define CV1 (CV0 + DD*192)
#define CV2 (CV1 + DD*96)
#define CV3 (CV2 + DD*DD)
#define CV4 (CV3 + DD*DFF)
#define CV5 (CV4 + DFF*DD)
#define CVT_TOTAL (CV5 + 288)

__global__ void cvt_all(const float* __restrict__ Wv, const float* __restrict__ Woff,
                        const float* __restrict__ Wattn, const float* __restrict__ Wout,
                        const float* __restrict__ Wff1, const float* __restrict__ Wff2,
                        const float* __restrict__ boff, const float* __restrict__ battn) {
    int idx = blockIdx.x * blockDim.x + threadIdx.x;
    if (idx >= CVT_TOTAL) return;
    if (idx < CV0) {
        int k = idx / DD, n = idx % DD;
        g_wvT[(size_t)n * DD + k] = __float2half(Wv[idx]);
    } else if (idx < CV1) {
        int i = idx - CV0;
        int k = i / 192, n = i % 192;
        g_woaT[(size_t)n * DD + k] = __float2half(Woff[i]);
    } else if (idx < CV2) {
        int i = idx - CV1;
        int k = i / 96, n = i % 96;
        g_woaT[(size_t)(192 + n) * DD + k] = __float2half(Wattn[i]);
    } else if (idx < CV3) {
        int i = idx - CV2;
        int k = i / DD, n = i % DD;
        g_woutT[(size_t)n * DD + k] = __float2half(Wout[i]);
    } else if (idx < CV4) {
        int i = idx - CV3;
        int k = i / DFF, n = i % DFF;
        g_wff1T[(size_t)n * DD + k] = __float2half(Wff1[i]);
    } else if (idx < CV5) {
        int i = idx - CV4;
        int k = i / DD, n = i % DD;
        g_wff2T[(size_t)n * DFF + k] = __float2half(Wff2[i]);
    } else {
        int i = idx - CV5;
        g_boa[i] = (i < 192) ? boff[i] : battn[i - 192];
    }
}

// ---------------- fused q = src+pos (fp16) and src->fp16 ----------------
__global__ void add_cvt_kernel(const float* __restrict__ src, const float* __restrict__ pos,
                               __half* __restrict__ qh, __half* __restrict__ srch, int n) {
    int i = blockIdx.x * blockDim.x + threadIdx.x;
    if (i < n) {
        float s = src[i];
        qh[i] = __float2half(s + pos[i]);
        srch[i] = __float2half(s);
    }
}

// ================= common GEMM helpers =================
#define BK 32
#define KPAD 40

__device__ __forceinline__ void cp_async16(void* smem_ptr, const void* gmem_ptr, bool valid) {
    uint32_t saddr = (uint32_t)__cvta_generic_to_shared(smem_ptr);
    int sz = valid ? 16 : 0;
    asm volatile("cp.async.cg.shared.global [%0], [%1], 16, %2;\n"
                 :: "r"(saddr), "l"(gmem_ptr), "r"(sz));
}
__device__ __forceinline__ void cp_async16r(uint32_t saddr, const void* gmem_ptr, bool valid) {
    int sz = valid ? 16 : 0;
    asm volatile("cp.async.cg.shared.global [%0], [%1], 16, %2;\n"
                 :: "r"(saddr), "l"(gmem_ptr), "r"(sz));
}
__device__ __forceinline__ void cp_commit() {
    asm volatile("cp.async.commit_group;\n");
}
template <int N>
__device__ __forceinline__ void cp_wait() {
    asm volatile("cp.async.wait_group %0;\n" :: "n"(N));
}
__device__ __forceinline__ void ldsm_x4(uint32_t& r0, uint32_t& r1, uint32_t& r2, uint32_t& r3,
                                        uint32_t addr) {
    asm volatile("ldmatrix.sync.aligned.m8n8.x4.shared.b16 {%0,%1,%2,%3}, [%4];"
                 : "=r"(r0), "=r"(r1), "=r"(r2), "=r"(r3) : "r"(addr));
}
__device__ __forceinline__ void ldsm_x2(uint32_t& r0, uint32_t& r1, uint32_t addr) {
    asm volatile("ldmatrix.sync.aligned.m8n8.x2.shared.b16 {%0,%1}, [%2];"
                 : "=r"(r0), "=r"(r1) : "r"(addr));
}
#define MMA16816(acc, afr, bfr) \
    asm volatile( \
        "mma.sync.aligned.m16n8k16.row.col.f32.f16.f16.f32 " \
        "{%0,%1,%2,%3}, {%4,%5,%6,%7}, {%8,%9}, {%0,%1,%2,%3};\n" \
        : "+f"((acc)[0]), "+f"((acc)[1]), "+f"((acc)[2]), "+f"((acc)[3]) \
        : "r"((afr)[0]), "r"((afr)[1]), "r"((afr)[2]), "r"((afr)[3]), \
          "r"((bfr)[0]), "r"((bfr)[1]))

// ================= generic FP16 GEMM (R8-proven: 128x128, 3-stage) =================
#define STAGES 3
#define TILE_HALVES (128 * KPAD)
#define GEMM_SMEM_BYTES (STAGES * 2 * TILE_HALVES * 2)

template <bool RELU, bool HALF_OUT>
__global__ void __launch_bounds__(256, 2)
gemm_f16(const __half* __restrict__ Aact,  // [Mdim][K]
         const __half* __restrict__ Wt,    // [N][K]
         const float* __restrict__ bias,
         float* __restrict__ C,
         __half* __restrict__ Ch,
         int Mdim, int N, int K) {
    extern __shared__ __half sm[];
    __half* As = sm;
    __half* Ws = sm + STAGES * TILE_HALVES;

    const int tid = threadIdx.x;
    const int lane = tid & 31;
    const int wid = tid >> 5;
    const int warpW = wid & 1;
    const int warpA = wid >> 1;
    const int g = lane >> 2;
    const int t4 = lane & 3;

    const int bm = blockIdx.y * 128;
    const int bn = blockIdx.x * 128;

    const int l_row = tid >> 1;
    const int l_kc0 = (tid & 1) * 2;

    const bool a_ok = (bm + l_row) < Mdim;
    const bool w_ok = (bn + l_row) < N;

    const int a_ld_off = (((lane >> 3) & 1) * 8 + (lane & 7)) * KPAD + ((lane >> 4) * 8);
    const int b_ld_off = ((lane & 7) * KPAD) + (((lane >> 3) & 1) * 8);

    float acc[4][4][4];
#pragma unroll
    for (int i = 0; i < 4; i++)
#pragma unroll
        for (int j = 0; j < 4; j++)
#pragma unroll
            for (int r = 0; r < 4; r++) acc[i][j][r] = 0.f;

    const int KT = K / BK;

    auto load_tile = [&](int kt, int s) {
        const int k0 = kt * BK;
        const __half* ag = Aact + (size_t)(bm + l_row) * K + k0 + l_kc0 * 8;
        const __half* wg = Wt + (size_t)(bn + l_row) * K + k0 + l_kc0 * 8;
        __half* as = As + s * TILE_HALVES + l_row * KPAD + l_kc0 * 8;
        __half* ws = Ws + s * TILE_HALVES + l_row * KPAD + l_kc0 * 8;
#pragma unroll
        for (int i = 0; i < 2; i++) {
            cp_async16(as + i * 8, ag + i * 8, a_ok);
            cp_async16(ws + i * 8, wg + i * 8, w_ok);
        }
        cp_commit();
    };

    load_tile(0, 0);
    if (KT > 1) load_tile(1, 1);

    for (int kt = 0; kt < KT; kt++) {
        if (kt + 1 < KT) cp_wait<1>();
        else cp_wait<0>();
        __syncthreads();

        if (kt + 2 < KT) load_tile(kt + 2, (kt + 2) % STAGES);

        const int s = kt % STAGES;
        const uint32_t asBase = (uint32_t)__cvta_generic_to_shared(As + s * TILE_HALVES);
        const uint32_t wsBase = (uint32_t)__cvta_generic_to_shared(Ws + s * TILE_HALVES);

#pragma unroll
        for (int ks = 0; ks < 2; ks++) {
            const int kb = ks * 16;
            uint32_t bfr[4][2];
#pragma unroll
            for (int nt = 0; nt < 4; nt++) {
                const uint32_t addr = asBase +
                    2 * ((warpA * 32 + nt * 8) * KPAD + kb + b_ld_off);
                ldsm_x2(bfr[nt][0], bfr[nt][1], addr);
            }
            uint32_t afr[4][4];
#pragma unroll
            for (int mt = 0; mt < 4; mt++) {
                const uint32_t addr = wsBase +
                    2 * ((warpW * 64 + mt * 16) * KPAD + kb + a_ld_off);
                ldsm_x4(afr[mt][0], afr[mt][1], afr[mt][2], afr[mt][3], addr);
            }
#pragma unroll
            for (int mt = 0; mt < 4; mt++)
#pragma unroll
                for (int nt = 0; nt < 4; nt++)
                    MMA16816(acc[mt][nt], afr[mt], bfr[nt]);
        }
    }

#pragma unroll
    for (int mt = 0; mt < 4; mt++) {
        const int wc = bn + warpW * 64 + mt * 16 + g;
        const bool c0ok = wc < N;
        const bool c8ok = (wc + 8) < N;
        const float b0 = c0ok ? bias[wc] : 0.f;
        const float b8 = c8ok ? bias[wc + 8] : 0.f;
#pragma unroll
        for (int nt = 0; nt < 4; nt++) {
            const int ar = bm + warpA * 32 + nt * 8 + 2 * t4;
#pragma unroll
            for (int half_i = 0; half_i < 2; half_i++) {
                const int r = ar + half_i;
                if (r >= Mdim) continue;
                float v0 = acc[mt][nt][0 + half_i] + b0;
                float v8 = acc[mt][nt][2 + half_i] + b8;
                if (RELU) { v0 = fmaxf(v0, 0.f); v8 = fmaxf(v8, 0.f); }
                if (HALF_OUT) {
                    if (c0ok) Ch[(size_t)r * N + wc] = __float2half(v0);
                    if (c8ok) Ch[(size_t)r * N + wc + 8] = __float2half(v8);
                } else {
                    if (c0ok) C[(size_t)r * N + wc] = v0;
                    if (c8ok) C[(size_t)r * N + wc + 8] = v8;
                }
            }
        }
    }
}

// ================= fused GEMM + bias + residual(fp16) + LayerNorm (N = 256) =================
// Block tile 64 rows x 256 cols. warpW = wid&3 (64 cols), warpA = wid>>2 (32 rows).
#define GLN_A_HALVES (64 * KPAD)
#define GLN_W_HALVES (256 * KPAD)
#define GLN_STAGE_HALVES (GLN_A_HALVES + GLN_W_HALVES)
#define GLN_SMEM_BYTES (STAGES * GLN_STAGE_HALVES * 2)

template <bool WRITE_F, bool WRITE_H>
__global__ void __launch_bounds__(256, 2)
gemm_ln_f16(const __half* __restrict__ Aact,   // [Mdim][K]
            const __half* __restrict__ Wt,     // [256][K]
            const float* __restrict__ bias,    // [256]
            const __half* __restrict__ ResidH, // [Mdim][256] fp16
            const float* __restrict__ gamma,
            const float* __restrict__ beta,
            float* __restrict__ OutF,
            __half* __restrict__ OutH,
            int Mdim, int K) {
    extern __shared__ __half sm[];
    __shared__ float2 lnb[64][4];

    const int tid = threadIdx.x;
    const int lane = tid & 31;
    const int wid = tid >> 5;
    const int warpW = wid & 3;
    const int warpA = wid >> 2;
    const int g = lane >> 2;
    const int t4 = lane & 3;

    const int bm = blockIdx.y * 64;

    const int a_ld_off = (((lane >> 3) & 1) * 8 + (lane & 7)) * KPAD + ((lane >> 4) * 8);
    const int b_ld_off = ((lane & 7) * KPAD) + (((lane >> 3) & 1) * 8);

    const uint32_t smBase = (uint32_t)__cvta_generic_to_shared(sm);

    float acc[4][4][4];
#pragma unroll
    for (int i = 0; i < 4; i++)
#pragma unroll
        for (int j = 0; j < 4; j++)
#pragma unroll
            for (int r = 0; r < 4; r++) acc[i][j][r] = 0.f;

    const int KT = K / BK;

    auto load_tile = [&](int kt, int s) {
        const int k0 = kt * BK;
        const uint32_t st = smBase + (uint32_t)(s * GLN_STAGE_HALVES * 2);
#pragma unroll
        for (int i = 0; i < 5; i++) {
            int c = tid + i * 256;
            if (c < 256) {
                int row = c >> 2, kc = c & 3;
                cp_async16r(st + (uint32_t)((row * KPAD + kc * 8) * 2),
                            Aact + (size_t)(bm + row) * K + k0 + kc * 8,
                            (bm + row) < Mdim);
            } else {
                int cc = c - 256;
                int row = cc >> 2, kc = cc & 3;
                cp_async16r(st + (uint32_t)((GLN_A_HALVES + row * KPAD + kc * 8) * 2),
                            Wt + (size_t)row * K + k0 + kc * 8, true);
            }
        }
        cp_commit();
    };

    load_tile(0, 0);
    if (KT > 1) load_tile(1, 1);

    for (int kt = 0; kt < KT; kt++) {
        if (kt + 1 < KT) cp_wait<1>();
        else cp_wait<0>();
        __syncthreads();

        if (kt + 2 < KT) load_tile(kt + 2, (kt + 2) % STAGES);

        const uint32_t asBase = smBase + (uint32_t)((kt % STAGES) * GLN_STAGE_HALVES * 2);
        const uint32_t wsBase = asBase + (uint32_t)(GLN_A_HALVES * 2);

#pragma unroll
        for (int ks = 0; ks < 2; ks++) {
            const int kb = ks * 16;
            uint32_t bfr[4][2];
#pragma unroll
            for (int nt = 0; nt < 4; nt++) {
                const uint32_t addr = asBase +
                    2 * ((warpA * 32 + nt * 8) * KPAD + kb + b_ld_off);
                ldsm_x2(bfr[nt][0], bfr[nt][1], addr);
            }
            uint32_t afr[4][4];
#pragma unroll
            for (int mt = 0; mt < 4; mt++) {
                const uint32_t addr = wsBase +
                    2 * ((warpW * 64 + mt * 16) * KPAD + kb + a_ld_off);
                ldsm_x4(afr[mt][0], afr[mt][1], afr[mt][2], afr[mt][3], addr);
            }
#pragma unroll
            for (int mt = 0; mt < 4; mt++)
#pragma unroll
                for (int nt = 0; nt < 4; nt++)
                    MMA16816(acc[mt][nt], afr[mt], bfr[nt]);
        }
    }

    // ---- fused epilogue ----
    float bcolv[4][2], gcol[4][2], betacol[4][2];
#pragma unroll
    for (int mt = 0; mt < 4; mt++)
#pragma unroll
        for (int ch = 0; ch < 2; ch++) {
            int col = warpW * 64 + mt * 16 + g + 8 * ch;
            bcolv[mt][ch] = bias[col];
            gcol[mt][ch] = gamma[col];
            betacol[mt][ch] = beta[col];
        }

    float s_arr[4][2], q_arr[4][2];
#pragma unroll
    for (int nt = 0; nt < 4; nt++)
#pragma unroll
        for (int hf = 0; hf < 2; hf++) {
            const int row = bm + warpA * 32 + nt * 8 + 2 * t4 + hf;
            const bool rok = row < Mdim;
            float ls = 0.f, lq = 0.f;
#pragma unroll
            for (int mt = 0; mt < 4; mt++)
#pragma unroll
                for (int ch = 0; ch < 2; ch++) {
                    const int col = warpW * 64 + mt * 16 + g + 8 * ch;
                    float v = acc[mt][nt][hf + 2 * ch] + bcolv[mt][ch];
                    if (rok) v += __half2float(ResidH[(size_t)row * 256 + col]);
                    acc[mt][nt][hf + 2 * ch] = v;
                    ls += v; lq += v * v;
                }
#pragma unroll
            for (int msk = 4; msk <= 16; msk <<= 1) {
                ls += __shfl_xor_sync(0xffffffffu, ls, msk);
                lq += __shfl_xor_sync(0xffffffffu, lq, msk);
            }
            s_arr[nt][hf] = ls;
            q_arr[nt][hf] = lq;
        }
    if (g == 0) {
#pragma unroll
        for (int nt = 0; nt < 4; nt++)
#pragma unroll
            for (int hf = 0; hf < 2; hf++) {
                int lrow = warpA * 32 + nt * 8 + 2 * t4 + hf;
                lnb[lrow][warpW] = make_float2(s_arr[nt][hf], q_arr[nt][hf]);
            }
    }
    __syncthreads();

#pragma unroll
    for (int nt = 0; nt < 4; nt++)
#pragma unroll
        for (int hf = 0; hf < 2; hf++) {
            const int lrow = warpA * 32 + nt * 8 + 2 * t4 + hf;
            const int row = bm + lrow;
            float ss = 0.f, qq = 0.f;
#pragma unroll
            for (int w = 0; w < 4; w++) {
                float2 p = lnb[lrow][w];
                ss += p.x; qq += p.y;
            }
            const float mean = ss * (1.f / 256.f);
            const float var = qq * (1.f / 256.f) - mean * mean;
            const float inv = rsqrtf(var + EPS);
            if (row < Mdim) {
#pragma unroll
                for (int mt = 0; mt < 4; mt++)
#pragma unroll
                    for (int ch = 0; ch < 2; ch++) {
                        const int col = warpW * 64 + mt * 16 + g + 8 * ch;
                        float r = (acc[mt][nt][hf + 2 * ch] - mean) * inv * gcol[mt][ch]
                                  + betacol[mt][ch];
                        if (WRITE_F) OutF[(size_t)row * 256 + col] = r;
                        if (WRITE_H) OutH[(size_t)row * 256 + col] = __float2half(r);
                    }
            }
        }
}

// ---------------- deformable attention core (fp16 value, half4 loads) ----------------
__global__ void __launch_bounds__(256)
deform_kernel(const __half* __restrict__ value,
              const float* __restrict__ refp,
              const float* __restrict__ offattn,
              __half* __restrict__ outh) {
    const int row = blockIdx.x;
    const int h = threadIdx.y;
    const int lane = threadIdx.x;
    const int b = row / LL;

    const float* oa = offattn + (size_t)row * 288;
    const float* lg = oa + 192 + h * 12;
    float lv = (lane < 12) ? lg[lane] : -INFINITY;
    float m = lv;
#pragma unroll
    for (int s = 16; s > 0; s >>= 1) m = fmaxf(m, __shfl_xor_sync(0xffffffffu, m, s));
    float e = (lane < 12) ? __expf(lv - m) : 0.f;
    float ssum = e;
#pragma unroll
    for (int s = 16; s > 0; s >>= 1) ssum += __shfl_xor_sync(0xffffffffu, ssum, s);
    float w12 = e / ssum;

    const float* offrow = oa + h * 24;
    const float* refrow = refp + (size_t)row * NLV * 2;
    const uint2* val4 = (const uint2*)value;

    const int pt = lane >> 3;
    const int cg = lane & 7;

    float4 acc = make_float4(0.f, 0.f, 0.f, 0.f);

#pragma unroll
    for (int l = 0; l < NLV; l++) {
        const int Hh = c_H[l], Ww = c_W[l], st = c_start[l];
        const int p = l * NPT + pt;
        const float rx = refrow[l * 2 + 0];
        const float ry = refrow[l * 2 + 1];
        const float ox = offrow[p * 2 + 0];
        const float oy = offrow[p * 2 + 1];
        const float aw = __shfl_sync(0xffffffffu, w12, p);

        float x = (rx + ox / (float)Ww) * (float)Ww - 0.5f;
        float y = (ry + oy / (float)Hh) * (float)Hh - 0.5f;
        float x0f = floorf(x), y0f = floorf(y);
        int x0 = (int)x0f, y0 = (int)y0f;
        int x1 = x0 + 1, y1 = y0 + 1;
        float wx1 = x - x0f, wy1 = y - y0f;
        float wx0 = 1.f - wx1, wy0 = 1.f - wy1;

        bool vx0 = (x0 >= 0) & (x0 < Ww);
        bool vx1 = (x1 >= 0) & (x1 < Ww);
        bool vy0 = (y0 >= 0) & (y0 < Hh);
        bool vy1 = (y1 >= 0) & (y1 < Hh);

        const size_t base = ((size_t)(b * LL + st)) * 64 + h * 8 + cg;
        uint2 u00 = make_uint2(0, 0), u10 = u00, u01 = u00, u11 = u00;
        if (vx0 & vy0) u00 = val4[base + (size_t)(y0 * Ww + x0) * 64];
        if (vx1 & vy0) u10 = val4[base + (size_t)(y0 * Ww + x1) * 64];
        if (vx0 & vy1) u01 = val4[base + (size_t)(y1 * Ww + x0) * 64];
        if (vx1 & vy1) u11 = val4[base + (size_t)(y1 * Ww + x1) * 64];

        const float w00 = wx0 * wy0 * aw, w10 = wx1 * wy0 * aw;
        const float w01 = wx0 * wy1 * aw, w11 = wx1 * wy1 * aw;

        float2 a0, a1;
        a0 = __half22float2(*(const __half2*)&u00.x);
        a1 = __half22float2(*(const __half2*)&u00.y);
        acc.x += a0.x * w00; acc.y += a0.y * w00; acc.z += a1.x * w00; acc.w += a1.y * w00;
        a0 = __half22float2(*(const __half2*)&u10.x);
        a1 = __half22float2(*(const __half2*)&u10.y);
        acc.x += a0.x * w10; acc.y += a0.y * w10; acc.z += a1.x * w10; acc.w += a1.y * w10;
        a0 = __half22float2(*(const __half2*)&u01.x);
        a1 = __half22float2(*(const __half2*)&u01.y);
        acc.x += a0.x * w01; acc.y += a0.y * w01; acc.z += a1.x * w01; acc.w += a1.y * w01;
        a0 = __half22float2(*(const __half2*)&u11.x);
        a1 = __half22float2(*(const __half2*)&u11.y);
        acc.x += a0.x * w11; acc.y += a0.y * w11; acc.z += a1.x * w11; acc.w += a1.y * w11;
    }

#pragma unroll
    for (int s = 8; s <= 16; s <<= 1) {
        acc.x += __shfl_xor_sync(0xffffffffu, acc.x, s);
        acc.y += __shfl_xor_sync(0xffffffffu, acc.y, s);
        acc.z += __shfl_xor_sync(0xffffffffu, acc.z, s);
        acc.w += __shfl_xor_sync(0xffffffffu, acc.w, s);
    }
    if (pt == 0) {
        __half2 h01 = __floats2half2_rn(acc.x, acc.y);
        __half2 h23 = __floats2half2_rn(acc.z, acc.w);
        __half2* dst = (__half2*)(outh + (size_t)row * DD + h * 32 + cg * 4);
        dst[0] = h01;
        dst[1] = h23;
    }
}

// ---------------- launch ----------------
extern "C" void kernel_launch(void* const* d_in, const int* in_sizes, int n_in,
                              void* d_out, int out_size) {
    const float* src  = (const float*)d_in[0];
    const float* pos  = (const float*)d_in[1];
    const float* refp = (const float*)d_in[2];
    const float* Wv   = (const float*)d_in[3];
    const float* bv   = (const float*)d_in[4];
    const float* Woff = (const float*)d_in[5];
    const float* boff = (const float*)d_in[6];
    const float* Wattn= (const float*)d_in[7];
    const float* battn= (const float*)d_in[8];
    const float* Wout = (const float*)d_in[9];
    const float* bout = (const float*)d_in[10];
    const float* g1   = (const float*)d_in[11];
    const float* b1   = (const float*)d_in[12];
    const float* Wff1 = (const float*)d_in[13];
    const float* bff1 = (const float*)d_in[14];
    const float* Wff2 = (const float*)d_in[15];
    const float* bff2 = (const float*)d_in[16];
    const float* g2   = (const float*)d_in[17];
    const float* b2   = (const float*)d_in[18];
    float* out = (float*)d_out;

    __half *qh, *srch, *valh, *samph, *xh, *hh;
    __half *wvT, *woaT, *woutT, *wff1T, *wff2T;
    float *offattn, *boa;
    cudaGetSymbolAddress((void**)&qh, g_qh);
    cudaGetSymbolAddress((void**)&srch, g_srch);
    cudaGetSymbolAddress((void**)&valh, g_valh);
    cudaGetSymbolAddress((void**)&offattn, g_offattn);
    cudaGetSymbolAddress((void**)&samph, g_samph);
    cudaGetSymbolAddress((void**)&xh, g_xh);
    cudaGetSymbolAddress((void**)&hh, g_hh);
    cudaGetSymbolAddress((void**)&wvT, g_wvT);
    cudaGetSymbolAddress((void**)&woaT, g_woaT);
    cudaGetSymbolAddress((void**)&woutT, g_woutT);
    cudaGetSymbolAddress((void**)&wff1T, g_wff1T);
    cudaGetSymbolAddress((void**)&wff2T, g_wff2T);
    cudaGetSymbolAddress((void**)&boa, g_boa);

    cudaFuncSetAttribute(gemm_f16<false, false>,
                         cudaFuncAttributeMaxDynamicSharedMemorySize, GEMM_SMEM_BYTES);
    cudaFuncSetAttribute(gemm_f16<false, true>,
                         cudaFuncAttributeMaxDynamicSharedMemorySize, GEMM_SMEM_BYTES);
    cudaFuncSetAttribute(gemm_f16<true, true>,
                         cudaFuncAttributeMaxDynamicSharedMemorySize, GEMM_SMEM_BYTES);
    cudaFuncSetAttribute(gemm_ln_f16<false, true>,
                         cudaFuncAttributeMaxDynamicSharedMemorySize, GLN_SMEM_BYTES);
    cudaFuncSetAttribute(gemm_ln_f16<true, false>,
                         cudaFuncAttributeMaxDynamicSharedMemorySize, GLN_SMEM_BYTES);

    cvt_all<<<(CVT_TOTAL + 255) / 256, 256>>>(Wv, Woff, Wattn, Wout, Wff1, Wff2, boff, battn);

    const int n = MM * DD;
    add_cvt_kernel<<<(n + 255) / 256, 256>>>(src, pos, qh, srch, n);

    dim3 blk(256);
    auto grid_for = [](int Mdim, int N) {
        return dim3((N + 127) / 128, (Mdim + 127) / 128);
    };

    // value = src @ Wv + bv (fp16 out)
    gemm_f16<false, true><<<grid_for(MM, DD), blk, GEMM_SMEM_BYTES>>>(srch, wvT, bv, nullptr, valh, MM, DD, DD);
    // off|attn = q @ [Woff|Wattn] + boa
    gemm_f16<false, false><<<grid_for(MM, 288), blk, GEMM_SMEM_BYTES>>>(qh, woaT, boa, offattn, nullptr, MM, 288, DD);

    deform_kernel<<<MM, dim3(32, 8)>>>(valh, refp, offattn, samph);

    // xh = LN(srch + samp @ Wout + bout) (fp16 only, fp16 residual)
    gemm_ln_f16<false, true><<<dim3(1, (MM + 63) / 64), blk, GLN_SMEM_BYTES>>>(
        samph, woutT, bout, srch, g1, b1, nullptr, xh, MM, DD);

    // h = relu(xh @ Wff1 + bff1) (fp16 out)
    gemm_f16<true, true><<<grid_for(MM, DFF), blk, GEMM_SMEM_BYTES>>>(xh, wff1T, bff1, nullptr, hh, MM, DFF, DD);

    // out = LN(xh + h @ Wff2 + bff2) (fp32 out, fp16 residual)
    gemm_ln_f16<true, false><<<dim3(1, (MM + 63) / 64), blk, GLN_SMEM_BYTES>>>(
        hh, wff2T, bff2, xh, g2, b2, out, nullptr, MM, DFF);
}

// round 13
// speedup vs baseline: 1.5867x; 1.5867x over previous
#include <cuda_runtime.h>
#include <cuda_fp16.h>
#include <cstdint>
#include <math.h>

// Problem constants
#define BB 4
#define LL 13125
#define MM (BB * LL)      // 52500 rows
#define DD 256
#define NH 8
#define HD 32
#define NLV 3
#define NPT 4
#define DFF 1024
#define EPS 1e-5f

__device__ __constant__ int c_H[NLV] = {100, 50, 25};
__device__ __constant__ int c_W[NLV] = {100, 50, 25};
__device__ __constant__ int c_start[NLV] = {0, 10000, 12500};

// ---------------- scratch ----------------
__device__ __half g_qh[MM * DD];
__device__ __half g_srch[MM * DD];
__device__ __half g_valh[MM * DD];
__device__ float  g_offattn[MM * 288];
__device__ __half g_samph[MM * DD];
__device__ __half g_xh[MM * DD];
__device__ __half g_hh[MM * DFF];
__device__ __half g_wvT[DD * DD];
__device__ __half g_woaT[288 * DD];
__device__ __half g_woutT[DD * DD];
__device__ __half g_wff1T[DFF * DD];
__device__ __half g_wff2T[DD * DFF];
__device__ float  g_boa[288];

// ---------------- fused weight convert/transpose + bias concat ----------------
#define CV0 (DD*DD)
#define CV1 (CV0 + DD*192)
#define CV2 (CV1 + DD*96)
#define CV3 (CV2 + DD*DD)
#define CV4 (CV3 + DD*DFF)
#define CV5 (CV4 + DFF*DD)
#define CVT_TOTAL (CV5 + 288)

__global__ void cvt_all(const float* __restrict__ Wv, const float* __restrict__ Woff,
                        const float* __restrict__ Wattn, const float* __restrict__ Wout,
                        const float* __restrict__ Wff1, const float* __restrict__ Wff2,
                        const float* __restrict__ boff, const float* __restrict__ battn) {
    int idx = blockIdx.x * blockDim.x + threadIdx.x;
    if (idx >= CVT_TOTAL) return;
    if (idx < CV0) {
        int k = idx / DD, n = idx % DD;
        g_wvT[(size_t)n * DD + k] = __float2half(Wv[idx]);
    } else if (idx < CV1) {
        int i = idx - CV0;
        int k = i / 192, n = i % 192;
        g_woaT[(size_t)n * DD + k] = __float2half(Woff[i]);
    } else if (idx < CV2) {
        int i = idx - CV1;
        int k = i / 96, n = i % 96;
        g_woaT[(size_t)(192 + n) * DD + k] = __float2half(Wattn[i]);
    } else if (idx < CV3) {
        int i = idx - CV2;
        int k = i / DD, n = i % DD;
        g_woutT[(size_t)n * DD + k] = __float2half(Wout[i]);
    } else if (idx < CV4) {
        int i = idx - CV3;
        int k = i / DFF, n = i % DFF;
        g_wff1T[(size_t)n * DD + k] = __float2half(Wff1[i]);
    } else if (idx < CV5) {
        int i = idx - CV4;
        int k = i / DD, n = i % DD;
        g_wff2T[(size_t)n * DFF + k] = __float2half(Wff2[i]);
    } else {
        int i = idx - CV5;
        g_boa[i] = (i < 192) ? boff[i] : battn[i - 192];
    }
}

// ---------------- fused q = src+pos (fp16) and src->fp16 (vectorized x4) ----------------
__global__ void add_cvt_kernel(const float4* __restrict__ src4, const float4* __restrict__ pos4,
                               __half2* __restrict__ qh2, __half2* __restrict__ srch2, int n4) {
    int i = blockIdx.x * blockDim.x + threadIdx.x;
    if (i < n4) {
        float4 s = src4[i];
        float4 p = pos4[i];
        srch2[2 * i + 0] = __floats2half2_rn(s.x, s.y);
        srch2[2 * i + 1] = __floats2half2_rn(s.z, s.w);
        qh2[2 * i + 0] = __floats2half2_rn(s.x + p.x, s.y + p.y);
        qh2[2 * i + 1] = __floats2half2_rn(s.z + p.z, s.w + p.w);
    }
}

// ================= common GEMM helpers =================
#define BK 32
#define KPAD 40

__device__ __forceinline__ void cp_async16(void* smem_ptr, const void* gmem_ptr, bool valid) {
    uint32_t saddr = (uint32_t)__cvta_generic_to_shared(smem_ptr);
    int sz = valid ? 16 : 0;
    asm volatile("cp.async.cg.shared.global [%0], [%1], 16, %2;\n"
                 :: "r"(saddr), "l"(gmem_ptr), "r"(sz));
}
__device__ __forceinline__ void cp_async16r(uint32_t saddr, const void* gmem_ptr, bool valid) {
    int sz = valid ? 16 : 0;
    asm volatile("cp.async.cg.shared.global [%0], [%1], 16, %2;\n"
                 :: "r"(saddr), "l"(gmem_ptr), "r"(sz));
}
__device__ __forceinline__ void cp_commit() {
    asm volatile("cp.async.commit_group;\n");
}
template <int N>
__device__ __forceinline__ void cp_wait() {
    asm volatile("cp.async.wait_group %0;\n" :: "n"(N));
}
__device__ __forceinline__ void ldsm_x4(uint32_t& r0, uint32_t& r1, uint32_t& r2, uint32_t& r3,
                                        uint32_t addr) {
    asm volatile("ldmatrix.sync.aligned.m8n8.x4.shared.b16 {%0,%1,%2,%3}, [%4];"
                 : "=r"(r0), "=r"(r1), "=r"(r2), "=r"(r3) : "r"(addr));
}
__device__ __forceinline__ void ldsm_x2(uint32_t& r0, uint32_t& r1, uint32_t addr) {
    asm volatile("ldmatrix.sync.aligned.m8n8.x2.shared.b16 {%0,%1}, [%2];"
                 : "=r"(r0), "=r"(r1) : "r"(addr));
}
#define MMA16816(acc, afr, bfr) \
    asm volatile( \
        "mma.sync.aligned.m16n8k16.row.col.f32.f16.f16.f32 " \
        "{%0,%1,%2,%3}, {%4,%5,%6,%7}, {%8,%9}, {%0,%1,%2,%3};\n" \
        : "+f"((acc)[0]), "+f"((acc)[1]), "+f"((acc)[2]), "+f"((acc)[3]) \
        : "r"((afr)[0]), "r"((afr)[1]), "r"((afr)[2]), "r"((afr)[3]), \
          "r"((bfr)[0]), "r"((bfr)[1]))

// ================= generic FP16 GEMM (128x128, 3-stage) =================
#define STAGES 3
#define TILE_HALVES (128 * KPAD)
#define GEMM_SMEM_BYTES (STAGES * 2 * TILE_HALVES * 2)

template <bool RELU, bool HALF_OUT>
__global__ void __launch_bounds__(256, 2)
gemm_f16(const __half* __restrict__ Aact,  // [Mdim][K]
         const __half* __restrict__ Wt,    // [N][K]
         const float* __restrict__ bias,
         float* __restrict__ C,
         __half* __restrict__ Ch,
         int Mdim, int N, int K) {
    extern __shared__ __half sm[];
    __half* As = sm;
    __half* Ws = sm + STAGES * TILE_HALVES;

    const int tid = threadIdx.x;
    const int lane = tid & 31;
    const int wid = tid >> 5;
    const int warpW = wid & 1;
    const int warpA = wid >> 1;
    const int g = lane >> 2;
    const int t4 = lane & 3;

    const int bm = blockIdx.y * 128;
    const int bn = blockIdx.x * 128;

    const int l_row = tid >> 1;
    const int l_kc0 = (tid & 1) * 2;

    const bool a_ok = (bm + l_row) < Mdim;
    const bool w_ok = (bn + l_row) < N;

    const int a_ld_off = (((lane >> 3) & 1) * 8 + (lane & 7)) * KPAD + ((lane >> 4) * 8);
    const int b_ld_off = ((lane & 7) * KPAD) + (((lane >> 3) & 1) * 8);

    float acc[4][4][4];
#pragma unroll
    for (int i = 0; i < 4; i++)
#pragma unroll
        for (int j = 0; j < 4; j++)
#pragma unroll
            for (int r = 0; r < 4; r++) acc[i][j][r] = 0.f;

    const int KT = K / BK;

    auto load_tile = [&](int kt, int s) {
        const int k0 = kt * BK;
        const __half* ag = Aact + (size_t)(bm + l_row) * K + k0 + l_kc0 * 8;
        const __half* wg = Wt + (size_t)(bn + l_row) * K + k0 + l_kc0 * 8;
        __half* as = As + s * TILE_HALVES + l_row * KPAD + l_kc0 * 8;
        __half* ws = Ws + s * TILE_HALVES + l_row * KPAD + l_kc0 * 8;
#pragma unroll
        for (int i = 0; i < 2; i++) {
            cp_async16(as + i * 8, ag + i * 8, a_ok);
            cp_async16(ws + i * 8, wg + i * 8, w_ok);
        }
        cp_commit();
    };

    load_tile(0, 0);
    if (KT > 1) load_tile(1, 1);

    for (int kt = 0; kt < KT; kt++) {
        if (kt + 1 < KT) cp_wait<1>();
        else cp_wait<0>();
        __syncthreads();

        if (kt + 2 < KT) load_tile(kt + 2, (kt + 2) % STAGES);

        const int s = kt % STAGES;
        const uint32_t asBase = (uint32_t)__cvta_generic_to_shared(As + s * TILE_HALVES);
        const uint32_t wsBase = (uint32_t)__cvta_generic_to_shared(Ws + s * TILE_HALVES);

#pragma unroll
        for (int ks = 0; ks < 2; ks++) {
            const int kb = ks * 16;
            uint32_t bfr[4][2];
#pragma unroll
            for (int nt = 0; nt < 4; nt++) {
                const uint32_t addr = asBase +
                    2 * ((warpA * 32 + nt * 8) * KPAD + kb + b_ld_off);
                ldsm_x2(bfr[nt][0], bfr[nt][1], addr);
            }
            uint32_t afr[4][4];
#pragma unroll
            for (int mt = 0; mt < 4; mt++) {
                const uint32_t addr = wsBase +
                    2 * ((warpW * 64 + mt * 16) * KPAD + kb + a_ld_off);
                ldsm_x4(afr[mt][0], afr[mt][1], afr[mt][2], afr[mt][3], addr);
            }
#pragma unroll
            for (int mt = 0; mt < 4; mt++)
#pragma unroll
                for (int nt = 0; nt < 4; nt++)
                    MMA16816(acc[mt][nt], afr[mt], bfr[nt]);
        }
    }

#pragma unroll
    for (int mt = 0; mt < 4; mt++) {
        const int wc = bn + warpW * 64 + mt * 16 + g;
        const bool c0ok = wc < N;
        const bool c8ok = (wc + 8) < N;
        const float b0 = c0ok ? bias[wc] : 0.f;
        const float b8 = c8ok ? bias[wc + 8] : 0.f;
#pragma unroll
        for (int nt = 0; nt < 4; nt++) {
            const int ar = bm + warpA * 32 + nt * 8 + 2 * t4;
#pragma unroll
            for (int half_i = 0; half_i < 2; half_i++) {
                const int r = ar + half_i;
                if (r >= Mdim) continue;
                float v0 = acc[mt][nt][0 + half_i] + b0;
                float v8 = acc[mt][nt][2 + half_i] + b8;
                if (RELU) { v0 = fmaxf(v0, 0.f); v8 = fmaxf(v8, 0.f); }
                if (HALF_OUT) {
                    if (c0ok) Ch[(size_t)r * N + wc] = __float2half(v0);
                    if (c8ok) Ch[(size_t)r * N + wc + 8] = __float2half(v8);
                } else {
                    if (c0ok) C[(size_t)r * N + wc] = v0;
                    if (c8ok) C[(size_t)r * N + wc + 8] = v8;
                }
            }
        }
    }
}

// ================= fused GEMM + bias + residual(fp16) + LayerNorm (N = 256) =================
#define GLN_A_HALVES (64 * KPAD)
#define GLN_W_HALVES (256 * KPAD)
#define GLN_STAGE_HALVES (GLN_A_HALVES + GLN_W_HALVES)
#define GLN_SMEM_BYTES (STAGES * GLN_STAGE_HALVES * 2)

template <bool WRITE_F, bool WRITE_H>
__global__ void __launch_bounds__(256, 2)
gemm_ln_f16(const __half* __restrict__ Aact,   // [Mdim][K]
            const __half* __restrict__ Wt,     // [256][K]
            const float* __restrict__ bias,    // [256]
            const __half* __restrict__ ResidH, // [Mdim][256] fp16
            const float* __restrict__ gamma,
            const float* __restrict__ beta,
            float* __restrict__ OutF,
            __half* __restrict__ OutH,
            int Mdim, int K) {
    extern __shared__ __half sm[];
    __shared__ float2 lnb[64][4];

    const int tid = threadIdx.x;
    const int lane = tid & 31;
    const int wid = tid >> 5;
    const int warpW = wid & 3;
    const int warpA = wid >> 2;
    const int g = lane >> 2;
    const int t4 = lane & 3;

    const int bm = blockIdx.y * 64;

    const int a_ld_off = (((lane >> 3) & 1) * 8 + (lane & 7)) * KPAD + ((lane >> 4) * 8);
    const int b_ld_off = ((lane & 7) * KPAD) + (((lane >> 3) & 1) * 8);

    const uint32_t smBase = (uint32_t)__cvta_generic_to_shared(sm);

    float acc[4][4][4];
#pragma unroll
    for (int i = 0; i < 4; i++)
#pragma unroll
        for (int j = 0; j < 4; j++)
#pragma unroll
            for (int r = 0; r < 4; r++) acc[i][j][r] = 0.f;

    const int KT = K / BK;

    auto load_tile = [&](int kt, int s) {
        const int k0 = kt * BK;
        const uint32_t st = smBase + (uint32_t)(s * GLN_STAGE_HALVES * 2);
#pragma unroll
        for (int i = 0; i < 5; i++) {
            int c = tid + i * 256;
            if (c < 256) {
                int row = c >> 2, kc = c & 3;
                cp_async16r(st + (uint32_t)((row * KPAD + kc * 8) * 2),
                            Aact + (size_t)(bm + row) * K + k0 + kc * 8,
                            (bm + row) < Mdim);
            } else {
                int cc = c - 256;
                int row = cc >> 2, kc = cc & 3;
                cp_async16r(st + (uint32_t)((GLN_A_HALVES + row * KPAD + kc * 8) * 2),
                            Wt + (size_t)row * K + k0 + kc * 8, true);
            }
        }
        cp_commit();
    };

    load_tile(0, 0);
    if (KT > 1) load_tile(1, 1);

    for (int kt = 0; kt < KT; kt++) {
        if (kt + 1 < KT) cp_wait<1>();
        else cp_wait<0>();
        __syncthreads();

        if (kt + 2 < KT) load_tile(kt + 2, (kt + 2) % STAGES);

        const uint32_t asBase = smBase + (uint32_t)((kt % STAGES) * GLN_STAGE_HALVES * 2);
        const uint32_t wsBase = asBase + (uint32_t)(GLN_A_HALVES * 2);

#pragma unroll
        for (int ks = 0; ks < 2; ks++) {
            const int kb = ks * 16;
            uint32_t bfr[4][2];
#pragma unroll
            for (int nt = 0; nt < 4; nt++) {
                const uint32_t addr = asBase +
                    2 * ((warpA * 32 + nt * 8) * KPAD + kb + b_ld_off);
                ldsm_x2(bfr[nt][0], bfr[nt][1], addr);
            }
            uint32_t afr[4][4];
#pragma unroll
            for (int mt = 0; mt < 4; mt++) {
                const uint32_t addr = wsBase +
                    2 * ((warpW * 64 + mt * 16) * KPAD + kb + a_ld_off);
                ldsm_x4(afr[mt][0], afr[mt][1], afr[mt][2], afr[mt][3], addr);
            }
#pragma unroll
            for (int mt = 0; mt < 4; mt++)
#pragma unroll
                for (int nt = 0; nt < 4; nt++)
                    MMA16816(acc[mt][nt], afr[mt], bfr[nt]);
        }
    }

    // ---- fused epilogue ----
    float bcolv[4][2], gcol[4][2], betacol[4][2];
#pragma unroll
    for (int mt = 0; mt < 4; mt++)
#pragma unroll
        for (int ch = 0; ch < 2; ch++) {
            int col = warpW * 64 + mt * 16 + g + 8 * ch;
            bcolv[mt][ch] = bias[col];
            gcol[mt][ch] = gamma[col];
            betacol[mt][ch] = beta[col];
        }

    float s_arr[4][2], q_arr[4][2];
#pragma unroll
    for (int nt = 0; nt < 4; nt++)
#pragma unroll
        for (int hf = 0; hf < 2; hf++) {
            const int row = bm + warpA * 32 + nt * 8 + 2 * t4 + hf;
            const bool rok = row < Mdim;
            float ls = 0.f, lq = 0.f;
#pragma unroll
            for (int mt = 0; mt < 4; mt++)
#pragma unroll
                for (int ch = 0; ch < 2; ch++) {
                    const int col = warpW * 64 + mt * 16 + g + 8 * ch;
                    float v = acc[mt][nt][hf + 2 * ch] + bcolv[mt][ch];
                    if (rok) v += __half2float(ResidH[(size_t)row * 256 + col]);
                    acc[mt][nt][hf + 2 * ch] = v;
                    ls += v; lq += v * v;
                }
#pragma unroll
            for (int msk = 4; msk <= 16; msk <<= 1) {
                ls += __shfl_xor_sync(0xffffffffu, ls, msk);
                lq += __shfl_xor_sync(0xffffffffu, lq, msk);
            }
            s_arr[nt][hf] = ls;
            q_arr[nt][hf] = lq;
        }
    if (g == 0) {
#pragma unroll
        for (int nt = 0; nt < 4; nt++)
#pragma unroll
            for (int hf = 0; hf < 2; hf++) {
                int lrow = warpA * 32 + nt * 8 + 2 * t4 + hf;
                lnb[lrow][warpW] = make_float2(s_arr[nt][hf], q_arr[nt][hf]);
            }
    }
    __syncthreads();

#pragma unroll
    for (int nt = 0; nt < 4; nt++)
#pragma unroll
        for (int hf = 0; hf < 2; hf++) {
            const int lrow = warpA * 32 + nt * 8 + 2 * t4 + hf;
            const int row = bm + lrow;
            float ss = 0.f, qq = 0.f;
#pragma unroll
            for (int w = 0; w < 4; w++) {
                float2 p = lnb[lrow][w];
                ss += p.x; qq += p.y;
            }
            const float mean = ss * (1.f / 256.f);
            const float var = qq * (1.f / 256.f) - mean * mean;
            const float inv = rsqrtf(var + EPS);
            if (row < Mdim) {
#pragma unroll
                for (int mt = 0; mt < 4; mt++)
#pragma unroll
                    for (int ch = 0; ch < 2; ch++) {
                        const int col = warpW * 64 + mt * 16 + g + 8 * ch;
                        float r = (acc[mt][nt][hf + 2 * ch] - mean) * inv * gcol[mt][ch]
                                  + betacol[mt][ch];
                        if (WRITE_F) OutF[(size_t)row * 256 + col] = r;
                        if (WRITE_H) OutH[(size_t)row * 256 + col] = __float2half(r);
                    }
            }
        }
}

// ---------------- deformable attention core (fp16 value, half4 loads) ----------------
__global__ void __launch_bounds__(256)
deform_kernel(const __half* __restrict__ value,
              const float* __restrict__ refp,
              const float* __restrict__ offattn,
              __half* __restrict__ outh) {
    const int row = blockIdx.x;
    const int h = threadIdx.y;
    const int lane = threadIdx.x;
    const int b = row / LL;

    const float* oa = offattn + (size_t)row * 288;
    const float* lg = oa + 192 + h * 12;
    float lv = (lane < 12) ? lg[lane] : -INFINITY;
    float m = lv;
#pragma unroll
    for (int s = 16; s > 0; s >>= 1) m = fmaxf(m, __shfl_xor_sync(0xffffffffu, m, s));
    float e = (lane < 12) ? __expf(lv - m) : 0.f;
    float ssum = e;
#pragma unroll
    for (int s = 16; s > 0; s >>= 1) ssum += __shfl_xor_sync(0xffffffffu, ssum, s);
    float w12 = e / ssum;

    const float* offrow = oa + h * 24;
    const float* refrow = refp + (size_t)row * NLV * 2;
    const uint2* val4 = (const uint2*)value;

    const int pt = lane >> 3;
    const int cg = lane & 7;

    float4 acc = make_float4(0.f, 0.f, 0.f, 0.f);

#pragma unroll
    for (int l = 0; l < NLV; l++) {
        const int Hh = c_H[l], Ww = c_W[l], st = c_start[l];
        const int p = l * NPT + pt;
        const float rx = refrow[l * 2 + 0];
        const float ry = refrow[l * 2 + 1];
        const float ox = offrow[p * 2 + 0];
        const float oy = offrow[p * 2 + 1];
        const float aw = __shfl_sync(0xffffffffu, w12, p);

        float x = (rx + ox / (float)Ww) * (float)Ww - 0.5f;
        float y = (ry + oy / (float)Hh) * (float)Hh - 0.5f;
        float x0f = floorf(x), y0f = floorf(y);
        int x0 = (int)x0f, y0 = (int)y0f;
        int x1 = x0 + 1, y1 = y0 + 1;
        float wx1 = x - x0f, wy1 = y - y0f;
        float wx0 = 1.f - wx1, wy0 = 1.f - wy1;

        bool vx0 = (x0 >= 0) & (x0 < Ww);
        bool vx1 = (x1 >= 0) & (x1 < Ww);
        bool vy0 = (y0 >= 0) & (y0 < Hh);
        bool vy1 = (y1 >= 0) & (y1 < Hh);

        const size_t base = ((size_t)(b * LL + st)) * 64 + h * 8 + cg;
        uint2 u00 = make_uint2(0, 0), u10 = u00, u01 = u00, u11 = u00;
        if (vx0 & vy0) u00 = val4[base + (size_t)(y0 * Ww + x0) * 64];
        if (vx1 & vy0) u10 = val4[base + (size_t)(y0 * Ww + x1) * 64];
        if (vx0 & vy1) u01 = val4[base + (size_t)(y1 * Ww + x0) * 64];
        if (vx1 & vy1) u11 = val4[base + (size_t)(y1 * Ww + x1) * 64];

        const float w00 = wx0 * wy0 * aw, w10 = wx1 * wy0 * aw;
        const float w01 = wx0 * wy1 * aw, w11 = wx1 * wy1 * aw;

        float2 a0, a1;
        a0 = __half22float2(*(const __half2*)&u00.x);
        a1 = __half22float2(*(const __half2*)&u00.y);
        acc.x += a0.x * w00; acc.y += a0.y * w00; acc.z += a1.x * w00; acc.w += a1.y * w00;
        a0 = __half22float2(*(const __half2*)&u10.x);
        a1 = __half22float2(*(const __half2*)&u10.y);
        acc.x += a0.x * w10; acc.y += a0.y * w10; acc.z += a1.x * w10; acc.w += a1.y * w10;
        a0 = __half22float2(*(const __half2*)&u01.x);
        a1 = __half22float2(*(const __half2*)&u01.y);
        acc.x += a0.x * w01; acc.y += a0.y * w01; acc.z += a1.x * w01; acc.w += a1.y * w01;
        a0 = __half22float2(*(const __half2*)&u11.x);
        a1 = __half22float2(*(const __half2*)&u11.y);
        acc.x += a0.x * w11; acc.y += a0.y * w11; acc.z += a1.x * w11; acc.w += a1.y * w11;
    }

#pragma unroll
    for (int s = 8; s <= 16; s <<= 1) {
        acc.x += __shfl_xor_sync(0xffffffffu, acc.x, s);
        acc.y += __shfl_xor_sync(0xffffffffu, acc.y, s);
        acc.z += __shfl_xor_sync(0xffffffffu, acc.z, s);
        acc.w += __shfl_xor_sync(0xffffffffu, acc.w, s);
    }
    if (pt == 0) {
        __half2 h01 = __floats2half2_rn(acc.x, acc.y);
        __half2 h23 = __floats2half2_rn(acc.z, acc.w);
        __half2* dst = (__half2*)(outh + (size_t)row * DD + h * 32 + cg * 4);
        dst[0] = h01;
        dst[1] = h23;
    }
}

// ---------------- launch ----------------
extern "C" void kernel_launch(void* const* d_in, const int* in_sizes, int n_in,
                              void* d_out, int out_size) {
    const float* src  = (const float*)d_in[0];
    const float* pos  = (const float*)d_in[1];
    const float* refp = (const float*)d_in[2];
    const float* Wv   = (const float*)d_in[3];
    const float* bv   = (const float*)d_in[4];
    const float* Woff = (const float*)d_in[5];
    const float* boff = (const float*)d_in[6];
    const float* Wattn= (const float*)d_in[7];
    const float* battn= (const float*)d_in[8];
    const float* Wout = (const float*)d_in[9];
    const float* bout = (const float*)d_in[10];
    const float* g1   = (const float*)d_in[11];
    const float* b1   = (const float*)d_in[12];
    const float* Wff1 = (const float*)d_in[13];
    const float* bff1 = (const float*)d_in[14];
    const float* Wff2 = (const float*)d_in[15];
    const float* bff2 = (const float*)d_in[16];
    const float* g2   = (const float*)d_in[17];
    const float* b2   = (const float*)d_in[18];
    float* out = (float*)d_out;

    __half *qh, *srch, *valh, *samph, *xh, *hh;
    __half *wvT, *woaT, *woutT, *wff1T, *wff2T;
    float *offattn, *boa;
    cudaGetSymbolAddress((void**)&qh, g_qh);
    cudaGetSymbolAddress((void**)&srch, g_srch);
    cudaGetSymbolAddress((void**)&valh, g_valh);
    cudaGetSymbolAddress((void**)&offattn, g_offattn);
    cudaGetSymbolAddress((void**)&samph, g_samph);
    cudaGetSymbolAddress((void**)&xh, g_xh);
    cudaGetSymbolAddress((void**)&hh, g_hh);
    cudaGetSymbolAddress((void**)&wvT, g_wvT);
    cudaGetSymbolAddress((void**)&woaT, g_woaT);
    cudaGetSymbolAddress((void**)&woutT, g_woutT);
    cudaGetSymbolAddress((void**)&wff1T, g_wff1T);
    cudaGetSymbolAddress((void**)&wff2T, g_wff2T);
    cudaGetSymbolAddress((void**)&boa, g_boa);

    cudaFuncSetAttribute(gemm_f16<false, false>,
                         cudaFuncAttributeMaxDynamicSharedMemorySize, GEMM_SMEM_BYTES);
    cudaFuncSetAttribute(gemm_f16<false, true>,
                         cudaFuncAttributeMaxDynamicSharedMemorySize, GEMM_SMEM_BYTES);
    cudaFuncSetAttribute(gemm_f16<true, true>,
                         cudaFuncAttributeMaxDynamicSharedMemorySize, GEMM_SMEM_BYTES);
    cudaFuncSetAttribute(gemm_ln_f16<false, true>,
                         cudaFuncAttributeMaxDynamicSharedMemorySize, GLN_SMEM_BYTES);
    cudaFuncSetAttribute(gemm_ln_f16<true, false>,
                         cudaFuncAttributeMaxDynamicSharedMemorySize, GLN_SMEM_BYTES);

    cvt_all<<<(CVT_TOTAL + 255) / 256, 256>>>(Wv, Woff, Wattn, Wout, Wff1, Wff2, boff, battn);

    const int n4 = MM * DD / 4;
    add_cvt_kernel<<<(n4 + 255) / 256, 256>>>((const float4*)src, (const float4*)pos,
                                              (__half2*)qh, (__half2*)srch, n4);

    dim3 blk(256);
    auto grid_for = [](int Mdim, int N) {
        return dim3((N + 127) / 128, (Mdim + 127) / 128);
    };

    // value = src @ Wv + bv (fp16 out)
    gemm_f16<false, true><<<grid_for(MM, DD), blk, GEMM_SMEM_BYTES>>>(srch, wvT, bv, nullptr, valh, MM, DD, DD);
    // off|attn = q @ [Woff|Wattn] + boa
    gemm_f16<false, false><<<grid_for(MM, 288), blk, GEMM_SMEM_BYTES>>>(qh, woaT, boa, offattn, nullptr, MM, 288, DD);

    deform_kernel<<<MM, dim3(32, 8)>>>(valh, refp, offattn, samph);

    // xh = LN(srch + samp @ Wout + bout) (fp16 only, fp16 residual)
    gemm_ln_f16<false, true><<<dim3(1, (MM + 63) / 64), blk, GLN_SMEM_BYTES>>>(
        samph, woutT, bout, srch, g1, b1, nullptr, xh, MM, DD);

    // h = relu(xh @ Wff1 + bff1) (fp16 out)
    gemm_f16<true, true><<<grid_for(MM, DFF), blk, GEMM_SMEM_BYTES>>>(xh, wff1T, bff1, nullptr, hh, MM, DFF, DD);

    // out = LN(xh + h @ Wff2 + bff2) (fp32 out, fp16 residual)
    gemm_ln_f16<true, false><<<dim3(1, (MM + 63) / 64), blk, GLN_SMEM_BYTES>>>(
        hh, wff2T, bff2, xh, g2, b2, out, nullptr, MM, DFF);
}